// round 2
// baseline (speedup 1.0000x reference)
#include <cuda_runtime.h>
#include <cstdint>

// ============================================================================
// relu(x @ W^T + b): M=131072, N=256, K=256, fp32.
// Target is base sm_103 (no tcgen05) -> Ampere-style mma.sync tf32 pipeline.
// CTA tile 64x256 (full N), KC=32, 2-stage cp.async, 8 warps x (32x64).
// ============================================================================

static constexpr int DK = 256;
static constexpr int DN = 256;
static constexpr int BM = 64;
static constexpr int KC = 32;                 // 32 fp32 = 128B row
static constexpr int THREADS = 256;

static constexpr int A_BYTES = BM * KC * 4;   // 8192
static constexpr int B_BYTES = DN * KC * 4;   // 32768
static constexpr int STAGE_BYTES = A_BYTES + B_BYTES;  // 40960
static constexpr int SMEM_DYN = 2 * STAGE_BYTES;       // 81920

// ---------------------------------------------------------------------------
__device__ __forceinline__ uint32_t smem_u32(const void* p) {
    uint32_t a;
    asm("{ .reg .u64 t; cvta.to.shared.u64 t, %1; cvt.u32.u64 %0, t; }" : "=r"(a) : "l"(p));
    return a;
}
__device__ __forceinline__ void cp_async16(uint32_t dst, const void* src) {
    asm volatile("cp.async.cg.shared.global [%0], [%1], 16;" :: "r"(dst), "l"(src));
}
__device__ __forceinline__ uint32_t lds_tf32(uint32_t addr) {
    float v;
    asm volatile("ld.shared.b32 %0, [%1];" : "=f"(v) : "r"(addr));
    uint32_t r;
    asm("cvt.rna.tf32.f32 %0, %1;" : "=r"(r) : "f"(v));
    return r;
}
__device__ __forceinline__ void mma_tf32(float* d, const uint32_t* a, const uint32_t* b) {
    asm volatile(
        "mma.sync.aligned.m16n8k8.row.col.f32.tf32.tf32.f32 "
        "{%0,%1,%2,%3}, {%4,%5,%6,%7}, {%8,%9}, {%0,%1,%2,%3};"
        : "+f"(d[0]), "+f"(d[1]), "+f"(d[2]), "+f"(d[3])
        : "r"(a[0]), "r"(a[1]), "r"(a[2]), "r"(a[3]), "r"(b[0]), "r"(b[1]));
}

// load one K-chunk (A 64x32 + B 256x32, fp32) into a stage with SW128 swizzle
__device__ __forceinline__ void load_chunk(const float* __restrict__ x,
                                           const float* __restrict__ W,
                                           int m0, int kc, uint32_t As, uint32_t Bs,
                                           int tid) {
    const int k0 = kc * KC;
    #pragma unroll
    for (int i = 0; i < 2; i++) {           // A: 512 float4
        int idx = i * 256 + tid;
        int row = idx >> 3, seg = idx & 7;
        const float* src = x + (size_t)(m0 + row) * DK + k0 + seg * 4;
        uint32_t dst = As + (uint32_t)row * 128u
                          + (uint32_t)((seg * 16) ^ ((row & 7) * 16));
        cp_async16(dst, src);
    }
    #pragma unroll
    for (int i = 0; i < 8; i++) {           // B: 2048 float4
        int idx = i * 256 + tid;
        int row = idx >> 3, seg = idx & 7;
        const float* src = W + (size_t)row * DK + k0 + seg * 4;
        uint32_t dst = Bs + (uint32_t)row * 128u
                          + (uint32_t)((seg * 16) ^ ((row & 7) * 16));
        cp_async16(dst, src);
    }
    asm volatile("cp.async.commit_group;" ::: "memory");
}

// ---------------------------------------------------------------------------
__global__ __launch_bounds__(THREADS, 2)
void gemm_relu_tf32_kernel(const float* __restrict__ x, const float* __restrict__ W,
                           const float* __restrict__ bias, float* __restrict__ out) {
    extern __shared__ __align__(1024) char smem_raw[];
    const uint32_t base = smem_u32(smem_raw);

    const int tid = threadIdx.x;
    const int wid = tid >> 5;
    const int lid = tid & 31;
    const int g   = lid >> 2;      // group-in-warp (row within 8-row frag)
    const int t   = lid & 3;       // thread-in-group (col within 4-col frag)
    const int wm  = wid & 1;       // warp m-tile (2 x 32 rows)
    const int wn  = wid >> 1;      // warp n-tile (4 x 64 cols)
    const int m0  = blockIdx.x * BM;

    float acc[2][8][4];
    #pragma unroll
    for (int mt = 0; mt < 2; mt++)
        #pragma unroll
        for (int nt = 0; nt < 8; nt++)
            #pragma unroll
            for (int j = 0; j < 4; j++) acc[mt][nt][j] = 0.0f;

    // prologue: chunks 0,1 into stages 0,1
    load_chunk(x, W, m0, 0, base, base + A_BYTES, tid);
    load_chunk(x, W, m0, 1, base + STAGE_BYTES, base + STAGE_BYTES + A_BYTES, tid);

    const uint32_t xor_g = (uint32_t)(g * 16);   // row&7 == g for all frag rows

    #pragma unroll
    for (int kc = 0; kc < 8; kc++) {
        if (kc < 6)
            asm volatile("cp.async.wait_group 1;" ::: "memory");
        else
            asm volatile("cp.async.wait_group 0;" ::: "memory");
        __syncthreads();

        const uint32_t As = base + (uint32_t)(kc & 1) * STAGE_BYTES;
        const uint32_t Bs = As + A_BYTES;

        #pragma unroll
        for (int kk = 0; kk < 4; kk++) {
            const uint32_t cb = (uint32_t)(kk * 32 + t * 4);
            uint32_t afr[2][4];
            #pragma unroll
            for (int mt = 0; mt < 2; mt++) {
                uint32_t r0 = (uint32_t)(wm * 32 + mt * 16 + g);
                uint32_t r1 = r0 + 8;
                afr[mt][0] = lds_tf32(As + r0 * 128u + (cb ^ xor_g));
                afr[mt][1] = lds_tf32(As + r1 * 128u + (cb ^ xor_g));
                afr[mt][2] = lds_tf32(As + r0 * 128u + ((cb + 16) ^ xor_g));
                afr[mt][3] = lds_tf32(As + r1 * 128u + ((cb + 16) ^ xor_g));
            }
            #pragma unroll
            for (int nt = 0; nt < 8; nt++) {
                uint32_t rb = (uint32_t)(wn * 64 + nt * 8 + g);
                uint32_t bfr[2];
                bfr[0] = lds_tf32(Bs + rb * 128u + (cb ^ xor_g));
                bfr[1] = lds_tf32(Bs + rb * 128u + ((cb + 16) ^ xor_g));
                mma_tf32(acc[0][nt], afr[0], bfr);
                mma_tf32(acc[1][nt], afr[1], bfr);
            }
        }
        __syncthreads();

        if (kc < 6) {
            uint32_t S = base + (uint32_t)(kc & 1) * STAGE_BYTES;
            load_chunk(x, W, m0, kc + 2, S, S + A_BYTES, tid);
        }
    }

    // ---- epilogue: bias + relu, float2 stores (sectors fully covered)
    const int m_base = m0 + wm * 32;
    const int n_base = wn * 64;
    #pragma unroll
    for (int nt = 0; nt < 8; nt++) {
        const int col = n_base + nt * 8 + 2 * t;
        const float2 bv = *reinterpret_cast<const float2*>(bias + col);
        #pragma unroll
        for (int mt = 0; mt < 2; mt++) {
            const int row0 = m_base + mt * 16 + g;
            float2 v0;
            v0.x = fmaxf(acc[mt][nt][0] + bv.x, 0.0f);
            v0.y = fmaxf(acc[mt][nt][1] + bv.y, 0.0f);
            *reinterpret_cast<float2*>(out + (size_t)row0 * DN + col) = v0;
            float2 v1;
            v1.x = fmaxf(acc[mt][nt][2] + bv.x, 0.0f);
            v1.y = fmaxf(acc[mt][nt][3] + bv.y, 0.0f);
            *reinterpret_cast<float2*>(out + (size_t)(row0 + 8) * DN + col) = v1;
        }
    }
}

// ---------------------------------------------------------------------------
extern "C" void kernel_launch(void* const* d_in, const int* in_sizes, int n_in,
                              void* d_out, int out_size) {
    const float* x = (const float*)d_in[0];
    const float* W = (const float*)d_in[1];
    const float* b = (const float*)d_in[2];
    float* out = (float*)d_out;

    int Brows = in_sizes[0] / DK;     // 131072
    int grid  = Brows / BM;           // 2048

    cudaFuncSetAttribute(gemm_relu_tf32_kernel,
                         cudaFuncAttributeMaxDynamicSharedMemorySize, SMEM_DYN);
    gemm_relu_tf32_kernel<<<grid, THREADS, SMEM_DYN>>>(x, W, b, out);
}

// round 3
// speedup vs baseline: 1.7341x; 1.7341x over previous
#include <cuda_runtime.h>
#include <cstdint>

// ============================================================================
// relu(x @ W^T + b): M=131072, N=256, K=256, fp32.
// Base sm_103 (no tcgen05) -> mma.sync.m16n8k8.tf32 pipeline.
// CTA tile 64x256 (full N), KC=32, 2-stage cp.async.
// Fragments via ldmatrix.x4.b16 over fp32 data (b16 pair == one fp32 element),
// cvt.rna.tf32 applied to register fragments (RNA precision preserved).
// ============================================================================

static constexpr int DK = 256;
static constexpr int DN = 256;
static constexpr int BM = 64;
static constexpr int KC = 32;                 // 32 fp32 = 128B row
static constexpr int THREADS = 256;

static constexpr int A_BYTES = BM * KC * 4;   // 8192
static constexpr int B_BYTES = DN * KC * 4;   // 32768
static constexpr int STAGE_BYTES = A_BYTES + B_BYTES;  // 40960
static constexpr int SMEM_DYN = 2 * STAGE_BYTES;       // 81920

// ---------------------------------------------------------------------------
__device__ __forceinline__ uint32_t smem_u32(const void* p) {
    uint32_t a;
    asm("{ .reg .u64 t; cvta.to.shared.u64 t, %1; cvt.u32.u64 %0, t; }" : "=r"(a) : "l"(p));
    return a;
}
__device__ __forceinline__ void cp_async16(uint32_t dst, const void* src) {
    asm volatile("cp.async.cg.shared.global [%0], [%1], 16;" :: "r"(dst), "l"(src));
}
__device__ __forceinline__ void ldsm_x4(uint32_t* d, uint32_t addr) {
    asm volatile("ldmatrix.sync.aligned.m8n8.x4.shared.b16 {%0,%1,%2,%3}, [%4];"
                 : "=r"(d[0]), "=r"(d[1]), "=r"(d[2]), "=r"(d[3]) : "r"(addr));
}
__device__ __forceinline__ uint32_t tf32(uint32_t v) {
    uint32_t r;
    asm("cvt.rna.tf32.f32 %0, %1;" : "=r"(r) : "f"(__uint_as_float(v)));
    return r;
}
__device__ __forceinline__ void mma_tf32(float* d, const uint32_t* a,
                                         uint32_t b0, uint32_t b1) {
    asm volatile(
        "mma.sync.aligned.m16n8k8.row.col.f32.tf32.tf32.f32 "
        "{%0,%1,%2,%3}, {%4,%5,%6,%7}, {%8,%9}, {%0,%1,%2,%3};"
        : "+f"(d[0]), "+f"(d[1]), "+f"(d[2]), "+f"(d[3])
        : "r"(a[0]), "r"(a[1]), "r"(a[2]), "r"(a[3]), "r"(b0), "r"(b1));
}

// load one K-chunk (A 64x32 + B 256x32, fp32) into a stage; XOR-16 swizzle
__device__ __forceinline__ void load_chunk(const float* __restrict__ x,
                                           const float* __restrict__ W,
                                           int m0, int kc, uint32_t As, uint32_t Bs,
                                           int tid) {
    const int k0 = kc * KC;
    #pragma unroll
    for (int i = 0; i < 2; i++) {           // A: 512 float4
        int idx = i * 256 + tid;
        int row = idx >> 3, seg = idx & 7;
        const float* src = x + (size_t)(m0 + row) * DK + k0 + seg * 4;
        uint32_t dst = As + (uint32_t)row * 128u
                          + (uint32_t)((seg * 16) ^ ((row & 7) * 16));
        cp_async16(dst, src);
    }
    #pragma unroll
    for (int i = 0; i < 8; i++) {           // B: 2048 float4
        int idx = i * 256 + tid;
        int row = idx >> 3, seg = idx & 7;
        const float* src = W + (size_t)row * DK + k0 + seg * 4;
        uint32_t dst = Bs + (uint32_t)row * 128u
                          + (uint32_t)((seg * 16) ^ ((row & 7) * 16));
        cp_async16(dst, src);
    }
    asm volatile("cp.async.commit_group;" ::: "memory");
}

// ---------------------------------------------------------------------------
__global__ __launch_bounds__(THREADS, 2)
void gemm_relu_tf32_kernel(const float* __restrict__ x, const float* __restrict__ W,
                           const float* __restrict__ bias, float* __restrict__ out) {
    extern __shared__ __align__(1024) char smem_raw[];
    const uint32_t base = smem_u32(smem_raw);

    const int tid = threadIdx.x;
    const int wid = tid >> 5;
    const int lid = tid & 31;
    const int g   = lid >> 2;      // mma row-in-frag
    const int t   = lid & 3;       // mma col-in-frag
    const int wm  = wid & 1;       // warp m-tile (2 x 32 rows)
    const int wn  = wid >> 1;      // warp n-tile (4 x 64 cols)
    const int m0  = blockIdx.x * BM;

    // ldmatrix lane role: matrix index m = lid>>3, row-in-matrix r = lid&7
    const int mx = lid >> 3;
    const int r  = lid & 7;
    const uint32_t xr = (uint32_t)(r * 16);

    // Per-thread LDSM base row offsets (bytes), before kk-dependent column:
    // A(mt): row = wm*32 + mt*16 + (mx&1)*8 + r ; sel = (mx>>1)*16
    // B(ntp): row = wn*64 + ntp*16 + (mx>>1)*8 + r ; sel = (mx&1)*16
    uint32_t a_row[2], b_row[4];
    #pragma unroll
    for (int mt = 0; mt < 2; mt++)
        a_row[mt] = (uint32_t)(wm * 32 + mt * 16 + (mx & 1) * 8 + r) * 128u;
    #pragma unroll
    for (int ntp = 0; ntp < 4; ntp++)
        b_row[ntp] = (uint32_t)(wn * 64 + ntp * 16 + (mx >> 1) * 8 + r) * 128u;
    const uint32_t a_sel = (uint32_t)((mx >> 1) * 16);
    const uint32_t b_sel = (uint32_t)((mx & 1) * 16);

    float acc[2][8][4];
    #pragma unroll
    for (int mt = 0; mt < 2; mt++)
        #pragma unroll
        for (int nt = 0; nt < 8; nt++)
            #pragma unroll
            for (int j = 0; j < 4; j++) acc[mt][nt][j] = 0.0f;

    // prologue: chunks 0,1 into stages 0,1
    load_chunk(x, W, m0, 0, base, base + A_BYTES, tid);
    load_chunk(x, W, m0, 1, base + STAGE_BYTES, base + STAGE_BYTES + A_BYTES, tid);

    #pragma unroll
    for (int kc = 0; kc < 8; kc++) {
        if (kc < 6)
            asm volatile("cp.async.wait_group 1;" ::: "memory");
        else
            asm volatile("cp.async.wait_group 0;" ::: "memory");
        __syncthreads();

        const uint32_t As = base + (uint32_t)(kc & 1) * STAGE_BYTES;
        const uint32_t Bs = As + A_BYTES;

        #pragma unroll
        for (int kk = 0; kk < 4; kk++) {
            const uint32_t acol = ((uint32_t)(kk * 32) + a_sel) ^ xr;
            const uint32_t bcol = ((uint32_t)(kk * 32) + b_sel) ^ xr;

            uint32_t a[2][4];
            #pragma unroll
            for (int mt = 0; mt < 2; mt++) {
                ldsm_x4(a[mt], As + a_row[mt] + acol);
                #pragma unroll
                for (int j = 0; j < 4; j++) a[mt][j] = tf32(a[mt][j]);
            }
            uint32_t bb[4][4];
            #pragma unroll
            for (int ntp = 0; ntp < 4; ntp++) {
                ldsm_x4(bb[ntp], Bs + b_row[ntp] + bcol);
                #pragma unroll
                for (int j = 0; j < 4; j++) bb[ntp][j] = tf32(bb[ntp][j]);
            }
            #pragma unroll
            for (int ntp = 0; ntp < 4; ntp++) {
                mma_tf32(acc[0][2 * ntp],     a[0], bb[ntp][0], bb[ntp][1]);
                mma_tf32(acc[1][2 * ntp],     a[1], bb[ntp][0], bb[ntp][1]);
                mma_tf32(acc[0][2 * ntp + 1], a[0], bb[ntp][2], bb[ntp][3]);
                mma_tf32(acc[1][2 * ntp + 1], a[1], bb[ntp][2], bb[ntp][3]);
            }
        }
        __syncthreads();

        if (kc < 6) {
            uint32_t S = base + (uint32_t)(kc & 1) * STAGE_BYTES;
            load_chunk(x, W, m0, kc + 2, S, S + A_BYTES, tid);
        }
    }

    // ---- epilogue: bias + relu, float2 stores
    const int m_base = m0 + wm * 32;
    const int n_base = wn * 64;
    #pragma unroll
    for (int nt = 0; nt < 8; nt++) {
        const int col = n_base + nt * 8 + 2 * t;
        const float2 bv = *reinterpret_cast<const float2*>(bias + col);
        #pragma unroll
        for (int mt = 0; mt < 2; mt++) {
            const int row0 = m_base + mt * 16 + g;
            float2 v0;
            v0.x = fmaxf(acc[mt][nt][0] + bv.x, 0.0f);
            v0.y = fmaxf(acc[mt][nt][1] + bv.y, 0.0f);
            *reinterpret_cast<float2*>(out + (size_t)row0 * DN + col) = v0;
            float2 v1;
            v1.x = fmaxf(acc[mt][nt][2] + bv.x, 0.0f);
            v1.y = fmaxf(acc[mt][nt][3] + bv.y, 0.0f);
            *reinterpret_cast<float2*>(out + (size_t)(row0 + 8) * DN + col) = v1;
        }
    }
}

// ---------------------------------------------------------------------------
extern "C" void kernel_launch(void* const* d_in, const int* in_sizes, int n_in,
                              void* d_out, int out_size) {
    const float* x = (const float*)d_in[0];
    const float* W = (const float*)d_in[1];
    const float* b = (const float*)d_in[2];
    float* out = (float*)d_out;

    int Brows = in_sizes[0] / DK;     // 131072
    int grid  = Brows / BM;           // 2048

    cudaFuncSetAttribute(gemm_relu_tf32_kernel,
                         cudaFuncAttributeMaxDynamicSharedMemorySize, SMEM_DYN);
    gemm_relu_tf32_kernel<<<grid, THREADS, SMEM_DYN>>>(x, W, b, out);
}